// round 9
// baseline (speedup 1.0000x reference)
#include <cuda_runtime.h>

// ---------------- problem constants (fixed shapes) ----------------
#define N_SRC1 200000
#define N_DST1 50000
#define N_DST2 10000
#define E1     2000000
#define E2     400000
#define IN_F   128
#define H_F    256
#define N_CLS  47

#define PAD1   50048   // N_DST1 padded to multiple of 128
#define PN     48      // padded layer-2 projected width

// ---------------- scratch (device globals; zero-initialized) ----------------
__device__ int   g_is64;
__device__ int   g_off1[N_DST1 + 1];
__device__ int   g_off2[N_DST2 + 1];
__device__ float g_hneigh1[(size_t)PAD1 * IN_F];   // layer1 mean-aggregated feats
__device__ float g_h[(size_t)PAD1 * H_F];          // layer1 output (relu'd)
__device__ float g_p[(size_t)PAD1 * PN];           // h @ Wneigh2 (projected, padded)
__device__ float g_pagg[(size_t)N_DST2 * PN];      // mean-aggregated p

// ---------------- index dtype detection ----------------
// src1 values are uniform-random in [0, 200000). If int64, every odd 32-bit
// word (high word) is zero; if int32, odd words are random and essentially
// surely nonzero among 128 samples.
__global__ void detect_kernel(const int* __restrict__ src1_raw) {
    if (threadIdx.x == 0) {
        int nz = 0;
        for (int i = 1; i < 256; i += 2) nz |= (src1_raw[i] != 0);
        g_is64 = nz ? 0 : 1;
    }
}

// ---------------- CSR offsets for both graphs via boundary scatter ----------------
// off[t] = lower_bound(dst, t): thread i owns all t with dst[i-1] < t <= dst[i].
__device__ __forceinline__ void scatter_one(const void* dst, int* off, int E,
                                            int ndst, int i, int is64) {
    int d, p;
    if (is64) {
        d = (int)((const long long*)dst)[i];
        p = (i == 0) ? -1 : (int)((const long long*)dst)[i - 1];
    } else {
        d = ((const int*)dst)[i];
        p = (i == 0) ? -1 : ((const int*)dst)[i - 1];
    }
    for (int t = p + 1; t <= d; ++t) off[t] = i;
    if (i == E - 1)
        for (int t = d + 1; t <= ndst; ++t) off[t] = E;
}

__global__ void offsets_kernel(const void* __restrict__ dst1,
                               const void* __restrict__ dst2) {
    int i = blockIdx.x * blockDim.x + threadIdx.x;
    int is64 = g_is64;
    if (i < E1) scatter_one(dst1, g_off1, E1, N_DST1, i, is64);
    if (i < E2) scatter_one(dst2, g_off2, E2, N_DST2, i, is64);
}

// ---------------- layer-1 aggregation: one warp per dst row, 128 feats ----------------
template <typename IT>
__device__ __forceinline__ void agg1_body(const float* __restrict__ x,
                                          const IT* __restrict__ src,
                                          int row, int lane) {
    int s = g_off1[row], e = g_off1[row + 1];
    float ax = 0.f, ay = 0.f, az = 0.f, aw = 0.f;
    int i = s;
    for (; i + 4 <= e; i += 4) {            // 4 gathers in flight
        int s0 = (int)__ldg(src + i),     s1 = (int)__ldg(src + i + 1);
        int s2 = (int)__ldg(src + i + 2), s3 = (int)__ldg(src + i + 3);
        float4 v0 = __ldg((const float4*)(x + (size_t)s0 * IN_F) + lane);
        float4 v1 = __ldg((const float4*)(x + (size_t)s1 * IN_F) + lane);
        float4 v2 = __ldg((const float4*)(x + (size_t)s2 * IN_F) + lane);
        float4 v3 = __ldg((const float4*)(x + (size_t)s3 * IN_F) + lane);
        ax += (v0.x + v1.x) + (v2.x + v3.x);
        ay += (v0.y + v1.y) + (v2.y + v3.y);
        az += (v0.z + v1.z) + (v2.z + v3.z);
        aw += (v0.w + v1.w) + (v2.w + v3.w);
    }
    for (; i < e; ++i) {
        int s0 = (int)__ldg(src + i);
        float4 v0 = __ldg((const float4*)(x + (size_t)s0 * IN_F) + lane);
        ax += v0.x; ay += v0.y; az += v0.z; aw += v0.w;
    }
    int deg = e - s;
    float sc = 1.0f / (float)(deg > 0 ? deg : 1);
    ((float4*)(g_hneigh1 + (size_t)row * IN_F))[lane] =
        make_float4(ax * sc, ay * sc, az * sc, aw * sc);
}

__global__ __launch_bounds__(256) void agg1_kernel(const float* __restrict__ x,
                                                   const void* __restrict__ srcv) {
    int row = (blockIdx.x * 256 + threadIdx.x) >> 5;
    if (row >= N_DST1) return;
    int lane = threadIdx.x & 31;
    if (g_is64) agg1_body<long long>(x, (const long long*)srcv, row, lane);
    else        agg1_body<int>(x, (const int*)srcv, row, lane);
}

// ---------------- layer-1 fused dual-GEMM + bias + relu ----------------
// g_h[m,n] = relu( x[m,:]@Wself[:,n] + hneigh1[m,:]@Wneigh[:,n] + b1[n] )
// K=256 concat GEMM: chunks 0..7 use (x, Wself), 8..15 use (hneigh1, Wneigh).
// BM=128 BN=128 BK=16, 256 threads, 8x8/thread, double-buffered smem with a
// SINGLE sync per chunk (prefetch -> compute -> write-next -> sync).
__global__ __launch_bounds__(256, 2) void gemm1_kernel(
    const float* __restrict__ x, const float* __restrict__ Wself,
    const float* __restrict__ Wneigh, const float* __restrict__ bias1) {
    __shared__ float As[2][16][136];    // transposed A tiles (k-major), padded
    __shared__ float Bs[2][16][128];

    const int bm = blockIdx.x * 128;
    const int bn = blockIdx.y * 128;
    const int tid = threadIdx.x;
    const int tx = tid & 15;            // cols bn + tx*8 .. +7
    const int ty = tid >> 4;            // rows bm + ty*8 .. +7
    const int ar = tid >> 1;            // A tile row 0..127
    const int akc = (tid & 1) * 8;      // A k-offset 0 or 8
    const int brow = tid >> 4;          // B k-row 0..15
    const int bnc = (tid & 15) * 8;     // B n-offset

    unsigned long long acc[8][4];
    #pragma unroll
    for (int i = 0; i < 8; i++)
        #pragma unroll
        for (int j = 0; j < 4; j++) acc[i][j] = 0ULL;

    // prologue: chunk 0 (x / Wself, k0 = 0) -> buf 0
    {
        const float* ap = x + (size_t)(bm + ar) * IN_F + akc;
        float4 a0 = *(const float4*)ap;
        float4 a1 = *(const float4*)(ap + 4);
        const float* wp = Wself + (size_t)brow * H_F + bn + bnc;
        float4 b0 = *(const float4*)wp;
        float4 b1 = *(const float4*)(wp + 4);
        As[0][akc + 0][ar] = a0.x; As[0][akc + 1][ar] = a0.y;
        As[0][akc + 2][ar] = a0.z; As[0][akc + 3][ar] = a0.w;
        As[0][akc + 4][ar] = a1.x; As[0][akc + 5][ar] = a1.y;
        As[0][akc + 6][ar] = a1.z; As[0][akc + 7][ar] = a1.w;
        float4* bd = (float4*)&Bs[0][brow][bnc];
        bd[0] = b0; bd[1] = b1;
    }
    __syncthreads();

    #pragma unroll 1
    for (int ch = 0; ch < 16; ++ch) {
        int buf = ch & 1;
        float4 pa0, pa1, pb0, pb1;
        if (ch < 15) {
            int chn = ch + 1;
            const float* Asel = (chn < 8) ? x : g_hneigh1;
            const float* Wsel = (chn < 8) ? Wself : Wneigh;
            int k0 = (chn & 7) * 16;
            const float* ap = Asel + (size_t)(bm + ar) * IN_F + k0 + akc;
            pa0 = *(const float4*)ap;
            pa1 = *(const float4*)(ap + 4);
            const float* wp = Wsel + (size_t)(k0 + brow) * H_F + bn + bnc;
            pb0 = *(const float4*)wp;
            pb1 = *(const float4*)(wp + 4);
        }
        #pragma unroll
        for (int k = 0; k < 16; ++k) {
            float av[8];
            #pragma unroll
            for (int i = 0; i < 8; i++) av[i] = As[buf][k][ty * 8 + i];
            const ulonglong2* bq = (const ulonglong2*)&Bs[buf][k][tx * 8];
            ulonglong2 q0 = bq[0], q1 = bq[1];
            unsigned long long bb[4] = {q0.x, q0.y, q1.x, q1.y};
            #pragma unroll
            for (int i = 0; i < 8; i++) {
                unsigned long long ad;
                asm("mov.b64 %0, {%1, %1};" : "=l"(ad) : "f"(av[i]));
                #pragma unroll
                for (int j = 0; j < 4; j++)
                    asm("fma.rn.f32x2 %0, %1, %2, %0;"
                        : "+l"(acc[i][j]) : "l"(ad), "l"(bb[j]));
            }
        }
        if (ch < 15) {
            int nb = buf ^ 1;
            // writes target the buffer whose readers all passed the previous
            // sync -> single sync per chunk is sufficient.
            As[nb][akc + 0][ar] = pa0.x; As[nb][akc + 1][ar] = pa0.y;
            As[nb][akc + 2][ar] = pa0.z; As[nb][akc + 3][ar] = pa0.w;
            As[nb][akc + 4][ar] = pa1.x; As[nb][akc + 5][ar] = pa1.y;
            As[nb][akc + 6][ar] = pa1.z; As[nb][akc + 7][ar] = pa1.w;
            float4* bd = (float4*)&Bs[nb][brow][bnc];
            bd[0] = pb0; bd[1] = pb1;
            __syncthreads();
        }
    }

    // epilogue: bias + relu -> g_h
    float4 bb0 = *(const float4*)(bias1 + bn + tx * 8);
    float4 bb1 = *(const float4*)(bias1 + bn + tx * 8 + 4);
    #pragma unroll
    for (int i = 0; i < 8; i++) {
        int m = bm + ty * 8 + i;                  // < PAD1 always
        float v[8];
        #pragma unroll
        for (int j = 0; j < 4; j++) {
            float lo, hi;
            asm("mov.b64 {%0, %1}, %2;" : "=f"(lo), "=f"(hi) : "l"(acc[i][j]));
            v[2 * j] = lo; v[2 * j + 1] = hi;
        }
        float4 r0, r1;
        r0.x = fmaxf(v[0] + bb0.x, 0.f); r0.y = fmaxf(v[1] + bb0.y, 0.f);
        r0.z = fmaxf(v[2] + bb0.z, 0.f); r0.w = fmaxf(v[3] + bb0.w, 0.f);
        r1.x = fmaxf(v[4] + bb1.x, 0.f); r1.y = fmaxf(v[5] + bb1.y, 0.f);
        r1.z = fmaxf(v[6] + bb1.z, 0.f); r1.w = fmaxf(v[7] + bb1.w, 0.f);
        float* op = g_h + (size_t)m * H_F + bn + tx * 8;
        *(float4*)op       = r0;
        *(float4*)(op + 4) = r1;
    }
}

// ---------------- small GEMM body: [128 rows, K=256] @ W[256, 47] ----------------
// MODE 0: p = Arows @ W            -> g_p  (padded to PN cols, col 47 = 0)
// MODE 1: out = Arows @ W + g_pagg + b2 -> out (rows < N_DST2, cols < 47)
// 256 threads; thread tile = 4 m-pairs x 3 n. m-pairs packed directly from
// transposed smem (LDS.64), so only 3 dup-movs per k. f32x2 accumulators.
template <int MODE>
__device__ __forceinline__ void small_gemm_body(
    const float* __restrict__ Arows, const float* __restrict__ W,
    const float* __restrict__ bias2, float* __restrict__ outp, int bm) {
    extern __shared__ float sm[];
    float* sW = sm;                    // [256][49]
    float* As = sm + 256 * 49;         // [2][16][136]

    const int tid = threadIdx.x;
    const int tx = tid & 15;           // n-group: cols tx*3 .. +2
    const int ty = tid >> 4;           // m rows ty*8 .. +7 (4 pairs)
    const int ar = tid >> 1;           // A tile row 0..127
    const int akc = (tid & 1) * 8;     // A k-offset 0 or 8

    unsigned long long acc[4][3];
    #pragma unroll
    for (int i = 0; i < 4; i++)
        #pragma unroll
        for (int j = 0; j < 3; j++) acc[i][j] = 0ULL;

    // stage full W (256 x 47) + zero pad col
    for (int idx = tid; idx < 256 * N_CLS; idx += 256) {
        int k = idx / N_CLS, n = idx - k * N_CLS;
        sW[k * 49 + n] = W[idx];
    }
    sW[tid * 49 + 47] = 0.f;

    // prologue: A chunk 0 -> buf 0 (transposed)
    {
        const float* ap = Arows + (size_t)(bm + ar) * H_F + akc;
        float4 a0 = *(const float4*)ap;
        float4 a1 = *(const float4*)(ap + 4);
        As[(akc + 0) * 136 + ar] = a0.x; As[(akc + 1) * 136 + ar] = a0.y;
        As[(akc + 2) * 136 + ar] = a0.z; As[(akc + 3) * 136 + ar] = a0.w;
        As[(akc + 4) * 136 + ar] = a1.x; As[(akc + 5) * 136 + ar] = a1.y;
        As[(akc + 6) * 136 + ar] = a1.z; As[(akc + 7) * 136 + ar] = a1.w;
    }
    __syncthreads();

    #pragma unroll 1
    for (int ch = 0; ch < 16; ++ch) {
        int buf = ch & 1;
        float4 pa0, pa1;
        if (ch < 15) {
            const float* ap = Arows + (size_t)(bm + ar) * H_F + (ch + 1) * 16 + akc;
            pa0 = *(const float4*)ap;
            pa1 = *(const float4*)(ap + 4);
        }
        const float* Ab = As + buf * (16 * 136);
        #pragma unroll
        for (int k = 0; k < 16; ++k) {
            const float* arow = Ab + k * 136 + ty * 8;
            unsigned long long a0 = *(const unsigned long long*)(arow + 0);
            unsigned long long a1 = *(const unsigned long long*)(arow + 2);
            unsigned long long a2 = *(const unsigned long long*)(arow + 4);
            unsigned long long a3 = *(const unsigned long long*)(arow + 6);
            const float* wr = sW + (ch * 16 + k) * 49 + tx * 3;
            float b0 = wr[0], b1 = wr[1], b2v = wr[2];
            unsigned long long bd0, bd1, bd2;
            asm("mov.b64 %0, {%1, %1};" : "=l"(bd0) : "f"(b0));
            asm("mov.b64 %0, {%1, %1};" : "=l"(bd1) : "f"(b1));
            asm("mov.b64 %0, {%1, %1};" : "=l"(bd2) : "f"(b2v));
            unsigned long long av[4] = {a0, a1, a2, a3};
            #pragma unroll
            for (int i = 0; i < 4; i++) {
                asm("fma.rn.f32x2 %0, %1, %2, %0;" : "+l"(acc[i][0]) : "l"(av[i]), "l"(bd0));
                asm("fma.rn.f32x2 %0, %1, %2, %0;" : "+l"(acc[i][1]) : "l"(av[i]), "l"(bd1));
                asm("fma.rn.f32x2 %0, %1, %2, %0;" : "+l"(acc[i][2]) : "l"(av[i]), "l"(bd2));
            }
        }
        if (ch < 15) {
            float* Ad = As + (buf ^ 1) * (16 * 136);
            Ad[(akc + 0) * 136 + ar] = pa0.x; Ad[(akc + 1) * 136 + ar] = pa0.y;
            Ad[(akc + 2) * 136 + ar] = pa0.z; Ad[(akc + 3) * 136 + ar] = pa0.w;
            Ad[(akc + 4) * 136 + ar] = pa1.x; Ad[(akc + 5) * 136 + ar] = pa1.y;
            Ad[(akc + 6) * 136 + ar] = pa1.z; Ad[(akc + 7) * 136 + ar] = pa1.w;
            __syncthreads();
        }
    }

    // epilogue
    #pragma unroll
    for (int i = 0; i < 4; i++) {
        int m0 = bm + ty * 8 + 2 * i;
        int m1 = m0 + 1;
        float lo[3], hi[3];
        #pragma unroll
        for (int j = 0; j < 3; j++)
            asm("mov.b64 {%0, %1}, %2;" : "=f"(lo[j]), "=f"(hi[j]) : "l"(acc[i][j]));
        if (MODE == 0) {
            #pragma unroll
            for (int j = 0; j < 3; j++) {
                g_p[(size_t)m0 * PN + tx * 3 + j] = lo[j];
                g_p[(size_t)m1 * PN + tx * 3 + j] = hi[j];
            }
        } else {
            if (m0 < N_DST2) {
                #pragma unroll
                for (int j = 0; j < 3; j++) {
                    int n = tx * 3 + j;
                    if (n < N_CLS)
                        outp[m0 * N_CLS + n] =
                            lo[j] + g_pagg[(size_t)m0 * PN + n] + __ldg(bias2 + n);
                }
            }
            if (m1 < N_DST2) {
                #pragma unroll
                for (int j = 0; j < 3; j++) {
                    int n = tx * 3 + j;
                    if (n < N_CLS)
                        outp[m1 * N_CLS + n] =
                            hi[j] + g_pagg[(size_t)m1 * PN + n] + __ldg(bias2 + n);
                }
            }
        }
    }
}

__global__ __launch_bounds__(256) void pgemm_kernel(const float* __restrict__ Wn2) {
    small_gemm_body<0>(g_h, Wn2, nullptr, nullptr, blockIdx.x * 128);
}
__global__ __launch_bounds__(256) void outgemm_kernel(const float* __restrict__ Ws2,
                                                      const float* __restrict__ b2,
                                                      float* __restrict__ out) {
    small_gemm_body<1>(g_h, Ws2, b2, out, blockIdx.x * 128);
}

// ---------------- layer-2 aggregation over projected feats (48 wide) ----------------
// 64 threads per dst row (lanes 0..47 active); mean over src rows of g_p.
template <typename IT>
__device__ __forceinline__ void aggp_body(const IT* __restrict__ src, int g, int t) {
    int s = g_off2[g], e = g_off2[g + 1];
    bool act = (t < PN);
    size_t to = t;
    float acc = 0.f;
    int i = s;
    for (; i + 4 <= e; i += 4) {
        int s0 = (int)__ldg(src + i),     s1 = (int)__ldg(src + i + 1);
        int s2 = (int)__ldg(src + i + 2), s3 = (int)__ldg(src + i + 3);
        if (act) {
            float v0 = __ldg((const float*)g_p + (size_t)s0 * PN + to);
            float v1 = __ldg((const float*)g_p + (size_t)s1 * PN + to);
            float v2 = __ldg((const float*)g_p + (size_t)s2 * PN + to);
            float v3 = __ldg((const float*)g_p + (size_t)s3 * PN + to);
            acc += (v0 + v1) + (v2 + v3);
        }
    }
    for (; i < e; ++i) {
        int s0 = (int)__ldg(src + i);
        if (act) acc += __ldg((const float*)g_p + (size_t)s0 * PN + to);
    }
    int deg = e - s;
    float sc = 1.0f / (float)(deg > 0 ? deg : 1);
    if (act) g_pagg[(size_t)g * PN + t] = acc * sc;
}

__global__ __launch_bounds__(256) void aggp_kernel(const void* __restrict__ srcv) {
    int g = (blockIdx.x * 256 + threadIdx.x) >> 6;
    if (g >= N_DST2) return;
    int t = threadIdx.x & 63;
    if (g_is64) aggp_body<long long>((const long long*)srcv, g, t);
    else        aggp_body<int>((const int*)srcv, g, t);
}

// ---------------- launch ----------------
extern "C" void kernel_launch(void* const* d_in, const int* in_sizes, int n_in,
                              void* d_out, int out_size) {
    const float* x       = (const float*)d_in[0];
    const float* Wself1  = (const float*)d_in[1];
    const float* Wneigh1 = (const float*)d_in[2];
    const float* b1      = (const float*)d_in[3];
    const float* Wself2  = (const float*)d_in[4];
    const float* Wneigh2 = (const float*)d_in[5];
    const float* b2      = (const float*)d_in[6];
    const void*  src1    = d_in[7];
    const void*  dst1    = d_in[8];
    const void*  src2    = d_in[9];
    const void*  dst2    = d_in[10];
    float* out = (float*)d_out;

    const int SMALL_SMEM = (256 * 49 + 2 * 16 * 136) * 4;   // 67584 B
    cudaFuncSetAttribute(pgemm_kernel,
                         cudaFuncAttributeMaxDynamicSharedMemorySize, SMALL_SMEM);
    cudaFuncSetAttribute(outgemm_kernel,
                         cudaFuncAttributeMaxDynamicSharedMemorySize, SMALL_SMEM);

    detect_kernel<<<1, 32>>>((const int*)src1);
    offsets_kernel<<<(E1 + 255) / 256, 256>>>(dst1, dst2);

    agg1_kernel<<<(N_DST1 + 7) / 8, 256>>>(x, src1);

    dim3 g1(PAD1 / 128, 2);
    gemm1_kernel<<<g1, 256>>>(x, Wself1, Wneigh1, b1);

    pgemm_kernel<<<PAD1 / 128, 256, SMALL_SMEM>>>(Wneigh2);

    aggp_kernel<<<(N_DST2 * 64) / 256, 256>>>(src2);

    outgemm_kernel<<<(N_DST2 + 127) / 128, 256, SMALL_SMEM>>>(Wself2, b2, out);
}